// round 15
// baseline (speedup 1.0000x reference)
#include <cuda_runtime.h>

// Problem constants (fixed by the reference setup_inputs)
#define BB 8
#define CC 512
#define RR 128
#define HW (128 * 128)
#define NPLANE (BB * CC)
#define HV (HW / 4 / 2)           // float4 elements per HALF plane (2048)

#define REDN 1024                 // red CTAs per batch (512 planes x 2 halves)
#define MIDN 16                   // mid CTAs per batch (16 x 8 warps = 128 rows)
#define ADDN 1024                 // add CTAs per batch
#define BLK  (2 * REDN + MIDN)    // interleaved add+red block, then mid (2064)
// Layout: red0 | mid0 | red1 | mid1 | 6 x BLK | add6 | add7
#define A0 (REDN)                 // 1024
#define A1 (A0 + MIDN)            // 1040
#define A2 (A1 + REDN)            // 2064
#define A3 (A2 + MIDN)            // 2080
#define A4 (A3 + 6 * BLK)         // 14464
#define GRID (A4 + 2 * ADDN)      // 16512

// Scratch (no allocations allowed in kernel_launch)
__device__ __align__(16) float g_part[NPLANE * 2];  // half-plane partial sums
__device__ __align__(16) float g_y1[BB * RR];       // relu6(w_guide @ mean)
__device__ int g_redCnt[BB];      // reds done per batch   (self-resetting)
__device__ int g_midArr[BB];      // mid tickets           (self-resetting)
__device__ int g_y1rdy[BB];       // mids done per batch   (self-resetting)
__device__ int g_addArr[BB];      // add tickets           (self-resetting)

// ---------------------------------------------------------------------------
// Half-plane reduce: one 256-thread CTA sums 8192 floats (8 float4/thread).
// Default-policy reads keep the batch L2-resident for its upcoming add.
// ---------------------------------------------------------------------------
__device__ __forceinline__ void half_reduce(const float* __restrict__ x,
                                            int plane, int half, int tid) {
    const float4* __restrict__ p =
        reinterpret_cast<const float4*>(x + (size_t)plane * HW) + half * HV;
    float s = 0.0f;
#pragma unroll
    for (int i = 0; i < HV / 256; ++i) {
        float4 v = p[tid + i * 256];
        s += (v.x + v.y) + (v.z + v.w);
    }
#pragma unroll
    for (int o = 16; o > 0; o >>= 1)
        s += __shfl_xor_sync(0xffffffffu, s, o);

    __shared__ float ws[8];
    if ((tid & 31) == 0) ws[tid >> 5] = s;
    __syncthreads();
    if (tid < 8) {
        float t = ws[tid];
#pragma unroll
        for (int o = 4; o > 0; o >>= 1)
            t += __shfl_xor_sync(0x000000ffu, t, o);
        if (tid == 0) g_part[plane * 2 + half] = t;
    }
}

// ---------------------------------------------------------------------------
// Half-plane add with inline bias (warp 0 dot + BN + relu6), then stream.
// Evict-first reads (dead after; frees L2 for the incoming batch) and stores.
// ---------------------------------------------------------------------------
__device__ __forceinline__ void half_add(
    const float* __restrict__ x, float* __restrict__ out,
    const float* __restrict__ w_fuse,
    const float* __restrict__ bn_gamma, const float* __restrict__ bn_beta,
    const float* __restrict__ bn_mean,  const float* __restrict__ bn_var,
    int b, int c, int half, int tid) {
    __shared__ float bsh;
    const int lane = tid & 31;

    if (tid < 32) {
        const float4* __restrict__ row =
            reinterpret_cast<const float4*>(w_fuse + (size_t)c * RR);
        const float4* __restrict__ y14 =
            reinterpret_cast<const float4*>(g_y1 + b * RR);
        float4 w = row[lane];
        float4 y = y14[lane];
        float acc = w.x * y.x;
        acc = fmaf(w.y, y.y, acc);
        acc = fmaf(w.z, y.z, acc);
        acc = fmaf(w.w, y.w, acc);
#pragma unroll
        for (int o = 16; o > 0; o >>= 1)
            acc += __shfl_xor_sync(0xffffffffu, acc, o);
        if (lane == 0) {
            const float inv_std = rsqrtf(bn_var[c] + 1e-5f);
            float v = fmaf((acc - bn_mean[c]) * inv_std, bn_gamma[c], bn_beta[c]);
            bsh = fminf(fmaxf(v, 0.0f), 6.0f);
        }
    }
    __syncthreads();
    const float bias = bsh;

    const int plane = b * CC + c;
    const float4* __restrict__ p =
        reinterpret_cast<const float4*>(x + (size_t)plane * HW) + half * HV;
    float4* __restrict__ o =
        reinterpret_cast<float4*>(out + (size_t)plane * HW) + half * HV;
#pragma unroll
    for (int i = 0; i < HV / 256; ++i) {
        float4 v = __ldcs(&p[tid + i * 256]);
        v.x += bias; v.y += bias; v.z += bias; v.w += bias;
        __stcs(&o[tid + i * 256], v);
    }
}

// ---------------------------------------------------------------------------
// Mid body: y1[b][r] = relu6((w_guide[r,:] @ sums[b]) / HW), one warp per r.
// ---------------------------------------------------------------------------
__device__ __forceinline__ void mid_body(const float* __restrict__ w_guide,
                                         int b, int r, int lane) {
    const float4* __restrict__ row =
        reinterpret_cast<const float4*>(w_guide + (size_t)r * CC);
    const float4* __restrict__ pp =
        reinterpret_cast<const float4*>(g_part + (size_t)b * CC * 2);

    float acc = 0.0f;
#pragma unroll
    for (int j = 0; j < 4; ++j) {
        float4 w  = row[lane + 32 * j];
        float4 a0 = pp[2 * (lane + 32 * j)];
        float4 a1 = pp[2 * (lane + 32 * j) + 1];
        acc = fmaf(w.x, a0.x + a0.y, acc);
        acc = fmaf(w.y, a0.z + a0.w, acc);
        acc = fmaf(w.z, a1.x + a1.y, acc);
        acc = fmaf(w.w, a1.z + a1.w, acc);
    }
#pragma unroll
    for (int o = 16; o > 0; o >>= 1)
        acc += __shfl_xor_sync(0xffffffffu, acc, o);
    if (lane == 0) {
        float v = acc * (1.0f / (float)HW);
        g_y1[b * RR + r] = fminf(fmaxf(v, 0.0f), 6.0f);
    }
}

// ---------------------------------------------------------------------------
// Role helpers with signalling (self-resetting counters for graph replay).
// ---------------------------------------------------------------------------
__device__ __forceinline__ void do_red(const float* __restrict__ x,
                                       int b, int i, int tid) {
    half_reduce(x, b * CC + (i >> 1), i & 1, tid);
    if (tid == 0) {
        __threadfence();
        atomicAdd(&g_redCnt[b], 1);
    }
}

__device__ __forceinline__ void do_mid(const float* __restrict__ w_guide,
                                       int b, int m, int tid) {
    if (tid == 0)
        while (*(volatile int*)&g_redCnt[b] < REDN) __nanosleep(64);
    __syncthreads();
    mid_body(w_guide, b, m * 8 + (tid >> 5), tid & 31);
    __syncthreads();
    if (tid == 0) {
        __threadfence();
        const int t = atomicAdd(&g_midArr[b], 1);
        atomicAdd(&g_y1rdy[b], 1);
        if (t == MIDN - 1) {            // last mid: reset red machinery
            g_redCnt[b] = 0;
            g_midArr[b] = 0;
        }
    }
}

__device__ __forceinline__ void do_add(
    const float* __restrict__ x, float* __restrict__ out,
    const float* __restrict__ w_fuse,
    const float* __restrict__ bn_gamma, const float* __restrict__ bn_beta,
    const float* __restrict__ bn_mean,  const float* __restrict__ bn_var,
    int b, int i, int tid) {
    if (tid == 0) {
        // y1(b) was produced >2000 bids earlier — this check normally falls
        // straight through; it exists as the correctness mechanism.
        while (*(volatile int*)&g_y1rdy[b] < MIDN) __nanosleep(64);
        const int u = atomicAdd(&g_addArr[b], 1);
        if (u == ADDN - 1) {            // last add: reset y1 machinery
            g_y1rdy[b]  = 0;
            g_addArr[b] = 0;
        }
    }
    __syncthreads();
    half_add(x, out, w_fuse, bn_gamma, bn_beta, bn_mean, bn_var,
             b, i >> 1, i & 1, tid);
}

// ---------------------------------------------------------------------------
// Mega kernel, spin-distance-stretched schedule:
//   red(0) | mid(0) | red(1) | mid(1)
//   b=0..5: [ even->add(b), odd->red(b+2) : 2048 ][ mid(b+2):16 ]
//   add(6) | add(7)
// Every add is dispatched >2000 CTAs after its y1 producer (beyond the
// ~1184-CTA in-flight window), so adds never spin. Only the 16 mid CTAs per
// batch spin (on the red tail just before them). Producers always precede
// consumers in bid order; root producers never wait -> no deadlock.
// ---------------------------------------------------------------------------
__global__ __launch_bounds__(256) void mega_kernel(
    const float* __restrict__ x, float* __restrict__ out,
    const float* __restrict__ w_guide,
    const float* __restrict__ w_fuse,
    const float* __restrict__ bn_gamma, const float* __restrict__ bn_beta,
    const float* __restrict__ bn_mean,  const float* __restrict__ bn_var) {
    const int bid = blockIdx.x;
    const int tid = threadIdx.x;

    if (bid < A0) {
        do_red(x, 0, bid, tid);
    } else if (bid < A1) {
        do_mid(w_guide, 0, bid - A0, tid);
    } else if (bid < A2) {
        do_red(x, 1, bid - A1, tid);
    } else if (bid < A3) {
        do_mid(w_guide, 1, bid - A2, tid);
    } else if (bid < A4) {
        const int t   = bid - A3;
        const int b   = t / BLK;              // 0..5
        const int off = t - b * BLK;
        if (off < 2 * REDN) {
            if (off & 1)
                do_red(x, b + 2, off >> 1, tid);
            else
                do_add(x, out, w_fuse, bn_gamma, bn_beta, bn_mean, bn_var,
                       b, off >> 1, tid);
        } else {
            do_mid(w_guide, b + 2, off - 2 * REDN, tid);
        }
    } else if (bid < A4 + ADDN) {
        do_add(x, out, w_fuse, bn_gamma, bn_beta, bn_mean, bn_var,
               6, bid - A4, tid);
    } else {
        do_add(x, out, w_fuse, bn_gamma, bn_beta, bn_mean, bn_var,
               7, bid - (A4 + ADDN), tid);
    }
}

extern "C" void kernel_launch(void* const* d_in, const int* in_sizes, int n_in,
                              void* d_out, int out_size) {
    const float* x        = (const float*)d_in[0];
    const float* w_guide  = (const float*)d_in[1];
    const float* w_fuse   = (const float*)d_in[2];
    const float* bn_gamma = (const float*)d_in[3];
    const float* bn_beta  = (const float*)d_in[4];
    const float* bn_mean  = (const float*)d_in[5];
    const float* bn_var   = (const float*)d_in[6];
    float* out = (float*)d_out;

    mega_kernel<<<GRID, 256>>>(x, out, w_guide, w_fuse,
                               bn_gamma, bn_beta, bn_mean, bn_var);
}

// round 16
// speedup vs baseline: 1.0394x; 1.0394x over previous
#include <cuda_runtime.h>

// Problem constants (fixed by the reference setup_inputs)
#define BB 8
#define CC 512
#define RR 128
#define HW (128 * 128)
#define NPLANE (BB * CC)
#define HV (HW / 4 / 2)           // float4 elements per HALF plane (2048)

#define SEGS 16                   // half-batch segments (256 planes each)
#define SRED 512                  // red (or add) CTAs per segment
#define MIDN 16                   // mid CTAs per batch
#define REDTOT 1024               // red CTAs per batch
#define ADDTOT 1024               // add CTAs per batch
#define NBLK 19
// Block k: red(h=k) if k<16, add(h=k-3) if 3<=k<19, interleaved;
//          mid(b=k>>1) appended when k odd && k<16.
__constant__ int BSTART[NBLK + 1] = {
    0, 512, 1040, 1552, 2592, 3616, 4656, 5680, 6720, 7744,
    8784, 9808, 10848, 11872, 12912, 13936, 14976, 15488, 16000, 16512};
#define GRID 16512

// Scratch (no allocations allowed in kernel_launch)
__device__ __align__(16) float g_part[NPLANE * 2];  // half-plane partial sums
__device__ __align__(16) float g_y1[BB * RR];       // relu6(w_guide @ mean)
__device__ int g_redCnt[BB];      // reds done per batch   (self-resetting)
__device__ int g_midArr[BB];      // mid tickets           (self-resetting)
__device__ int g_y1rdy[BB];       // mids done per batch   (self-resetting)
__device__ int g_addArr[BB];      // add tickets           (self-resetting)

// ---------------------------------------------------------------------------
// Half-plane reduce: one 256-thread CTA sums 8192 floats (8 float4/thread).
// Default-policy reads keep the batch L2-resident for its upcoming add.
// ---------------------------------------------------------------------------
__device__ __forceinline__ void half_reduce(const float* __restrict__ x,
                                            int plane, int half, int tid) {
    const float4* __restrict__ p =
        reinterpret_cast<const float4*>(x + (size_t)plane * HW) + half * HV;
    float s = 0.0f;
#pragma unroll
    for (int i = 0; i < HV / 256; ++i) {
        float4 v = p[tid + i * 256];
        s += (v.x + v.y) + (v.z + v.w);
    }
#pragma unroll
    for (int o = 16; o > 0; o >>= 1)
        s += __shfl_xor_sync(0xffffffffu, s, o);

    __shared__ float ws[8];
    if ((tid & 31) == 0) ws[tid >> 5] = s;
    __syncthreads();
    if (tid < 8) {
        float t = ws[tid];
#pragma unroll
        for (int o = 4; o > 0; o >>= 1)
            t += __shfl_xor_sync(0x000000ffu, t, o);
        if (tid == 0) g_part[plane * 2 + half] = t;
    }
}

// ---------------------------------------------------------------------------
// Half-plane add with inline bias (warp 0 dot + BN + relu6), then stream.
// Evict-first reads (dead after; frees L2 for the incoming segments) & stores.
// ---------------------------------------------------------------------------
__device__ __forceinline__ void half_add(
    const float* __restrict__ x, float* __restrict__ out,
    const float* __restrict__ w_fuse,
    const float* __restrict__ bn_gamma, const float* __restrict__ bn_beta,
    const float* __restrict__ bn_mean,  const float* __restrict__ bn_var,
    int b, int c, int half, int tid) {
    __shared__ float bsh;
    const int lane = tid & 31;

    if (tid < 32) {
        const float4* __restrict__ row =
            reinterpret_cast<const float4*>(w_fuse + (size_t)c * RR);
        const float4* __restrict__ y14 =
            reinterpret_cast<const float4*>(g_y1 + b * RR);
        float4 w = row[lane];
        float4 y = y14[lane];
        float acc = w.x * y.x;
        acc = fmaf(w.y, y.y, acc);
        acc = fmaf(w.z, y.z, acc);
        acc = fmaf(w.w, y.w, acc);
#pragma unroll
        for (int o = 16; o > 0; o >>= 1)
            acc += __shfl_xor_sync(0xffffffffu, acc, o);
        if (lane == 0) {
            const float inv_std = rsqrtf(bn_var[c] + 1e-5f);
            float v = fmaf((acc - bn_mean[c]) * inv_std, bn_gamma[c], bn_beta[c]);
            bsh = fminf(fmaxf(v, 0.0f), 6.0f);
        }
    }
    __syncthreads();
    const float bias = bsh;

    const int plane = b * CC + c;
    const float4* __restrict__ p =
        reinterpret_cast<const float4*>(x + (size_t)plane * HW) + half * HV;
    float4* __restrict__ o =
        reinterpret_cast<float4*>(out + (size_t)plane * HW) + half * HV;
#pragma unroll
    for (int i = 0; i < HV / 256; ++i) {
        float4 v = __ldcs(&p[tid + i * 256]);
        v.x += bias; v.y += bias; v.z += bias; v.w += bias;
        __stcs(&o[tid + i * 256], v);
    }
}

// ---------------------------------------------------------------------------
// Mid body: y1[b][r] = relu6((w_guide[r,:] @ sums[b]) / HW), one warp per r.
// ---------------------------------------------------------------------------
__device__ __forceinline__ void mid_body(const float* __restrict__ w_guide,
                                         int b, int r, int lane) {
    const float4* __restrict__ row =
        reinterpret_cast<const float4*>(w_guide + (size_t)r * CC);
    const float4* __restrict__ pp =
        reinterpret_cast<const float4*>(g_part + (size_t)b * CC * 2);

    float acc = 0.0f;
#pragma unroll
    for (int j = 0; j < 4; ++j) {
        float4 w  = row[lane + 32 * j];
        float4 a0 = pp[2 * (lane + 32 * j)];
        float4 a1 = pp[2 * (lane + 32 * j) + 1];
        acc = fmaf(w.x, a0.x + a0.y, acc);
        acc = fmaf(w.y, a0.z + a0.w, acc);
        acc = fmaf(w.z, a1.x + a1.y, acc);
        acc = fmaf(w.w, a1.z + a1.w, acc);
    }
#pragma unroll
    for (int o = 16; o > 0; o >>= 1)
        acc += __shfl_xor_sync(0xffffffffu, acc, o);
    if (lane == 0) {
        float v = acc * (1.0f / (float)HW);
        g_y1[b * RR + r] = fminf(fmaxf(v, 0.0f), 6.0f);
    }
}

// ---------------------------------------------------------------------------
// Role helpers with signalling (self-resetting counters for graph replay).
// h = half-batch segment index (0..15): batch b = h>>1, channel base
// (h&1)*256; i in [0,512) selects plane (i>>1) and half (i&1).
// ---------------------------------------------------------------------------
__device__ __forceinline__ void do_red(const float* __restrict__ x,
                                       int h, int i, int tid) {
    const int b = h >> 1;
    half_reduce(x, b * CC + (h & 1) * (CC / 2) + (i >> 1), i & 1, tid);
    if (tid == 0) {
        __threadfence();
        atomicAdd(&g_redCnt[b], 1);
    }
}

__device__ __forceinline__ void do_mid(const float* __restrict__ w_guide,
                                       int b, int m, int tid) {
    if (tid == 0)
        while (*(volatile int*)&g_redCnt[b] < REDTOT) __nanosleep(64);
    __syncthreads();
    mid_body(w_guide, b, m * 8 + (tid >> 5), tid & 31);
    __syncthreads();
    if (tid == 0) {
        __threadfence();
        const int t = atomicAdd(&g_midArr[b], 1);
        atomicAdd(&g_y1rdy[b], 1);
        if (t == MIDN - 1) {            // last mid: reset red machinery
            g_redCnt[b] = 0;
            g_midArr[b] = 0;
        }
    }
}

__device__ __forceinline__ void do_add(
    const float* __restrict__ x, float* __restrict__ out,
    const float* __restrict__ w_fuse,
    const float* __restrict__ bn_gamma, const float* __restrict__ bn_beta,
    const float* __restrict__ bn_mean,  const float* __restrict__ bn_var,
    int h, int i, int tid) {
    const int b = h >> 1;
    if (tid == 0) {
        while (*(volatile int*)&g_y1rdy[b] < MIDN) __nanosleep(64);
        const int u = atomicAdd(&g_addArr[b], 1);
        if (u == ADDTOT - 1) {          // last add: reset y1 machinery
            g_y1rdy[b]  = 0;
            g_addArr[b] = 0;
        }
    }
    __syncthreads();
    half_add(x, out, w_fuse, bn_gamma, bn_beta, bn_mean, bn_var,
             b, (h & 1) * (CC / 2) + (i >> 1), i & 1, tid);
}

// ---------------------------------------------------------------------------
// Mega kernel, half-batch depth-3 pipeline:
//   block k (k=0..18): [add(h=k-3) (even bids) interleaved with red(h=k)
//   (odd bids)], then mid(b=k>>1) when k is odd (<16).
// add trails red by 3 segments: far enough in bid-order that y1 is done by
// dispatch time (no spins), close enough that x stays L2-resident (~67MB
// working set). Producers precede consumers in bid order; roots never wait.
// ---------------------------------------------------------------------------
__global__ __launch_bounds__(256) void mega_kernel(
    const float* __restrict__ x, float* __restrict__ out,
    const float* __restrict__ w_guide,
    const float* __restrict__ w_fuse,
    const float* __restrict__ bn_gamma, const float* __restrict__ bn_beta,
    const float* __restrict__ bn_mean,  const float* __restrict__ bn_var) {
    const int bid = blockIdx.x;
    const int tid = threadIdx.x;

    int k = 0;
    while (bid >= BSTART[k + 1]) ++k;       // <=19 constant-mem iterations
    const int off = bid - BSTART[k];

    const bool hasRed = (k < SEGS);
    const bool hasAdd = (k >= 3);
    const int nStream = (hasRed ? SRED : 0) + (hasAdd ? SRED : 0);

    if (off < nStream) {
        if (hasRed && hasAdd) {
            const int i = off >> 1;
            if (off & 1)
                do_red(x, k, i, tid);
            else
                do_add(x, out, w_fuse, bn_gamma, bn_beta, bn_mean, bn_var,
                       k - 3, i, tid);
        } else if (hasRed) {
            do_red(x, k, off, tid);
        } else {
            do_add(x, out, w_fuse, bn_gamma, bn_beta, bn_mean, bn_var,
                   k - 3, off, tid);
        }
    } else {
        // mid CTAs: appended to odd blocks k (k<16), batch b = k>>1
        do_mid(w_guide, k >> 1, off - nStream, tid);
    }
}

extern "C" void kernel_launch(void* const* d_in, const int* in_sizes, int n_in,
                              void* d_out, int out_size) {
    const float* x        = (const float*)d_in[0];
    const float* w_guide  = (const float*)d_in[1];
    const float* w_fuse   = (const float*)d_in[2];
    const float* bn_gamma = (const float*)d_in[3];
    const float* bn_beta  = (const float*)d_in[4];
    const float* bn_mean  = (const float*)d_in[5];
    const float* bn_var   = (const float*)d_in[6];
    float* out = (float*)d_out;

    mega_kernel<<<GRID, 256>>>(x, out, w_guide, w_fuse,
                               bn_gamma, bn_beta, bn_mean, bn_var);
}

// round 17
// speedup vs baseline: 1.0740x; 1.0333x over previous
#include <cuda_runtime.h>

// Problem constants (fixed by the reference setup_inputs)
#define BB 8
#define CC 512
#define RR 128
#define HW (128 * 128)
#define NPLANE (BB * CC)
#define HV (HW / 4 / 2)           // float4 elements per HALF plane (2048)

#define SEGS 16                   // half-batch segments (256 planes each)
#define SRED 512                  // red (or add) CTAs per segment
#define MIDN 16                   // mid CTAs per batch
#define REDTOT 1024               // red CTAs per batch
#define ADDTOT 1024               // add CTAs per batch
#define NBLK 18
// Block k: red(h=k) if k<16, add(h=k-2) if k>=2, interleaved;
//          mid(b=k>>1) appended when k odd && k<16.
__constant__ int BSTART[NBLK + 1] = {
    0, 512, 1040, 2064, 3104, 4128, 5168, 6192, 7232, 8256,
    9296, 10320, 11360, 12384, 13424, 14448, 15488, 16000, 16512};
#define GRID 16512

// Scratch (no allocations allowed in kernel_launch)
__device__ __align__(16) float g_part[NPLANE * 2];  // half-plane partial sums
__device__ __align__(16) float g_y1[BB * RR];       // relu6(w_guide @ mean)
__device__ int g_redCnt[BB];      // reds done per batch   (self-resetting)
__device__ int g_midArr[BB];      // mid tickets           (self-resetting)
__device__ int g_y1rdy[BB];       // mids done per batch   (self-resetting)
__device__ int g_addArr[BB];      // add tickets           (self-resetting)

// ---------------------------------------------------------------------------
// Half-plane reduce: one 256-thread CTA sums 8192 floats (8 float4/thread).
// Default-policy reads keep the batch L2-resident for its upcoming add.
// ---------------------------------------------------------------------------
__device__ __forceinline__ void half_reduce(const float* __restrict__ x,
                                            int plane, int half, int tid) {
    const float4* __restrict__ p =
        reinterpret_cast<const float4*>(x + (size_t)plane * HW) + half * HV;
    float s = 0.0f;
#pragma unroll
    for (int i = 0; i < HV / 256; ++i) {
        float4 v = p[tid + i * 256];
        s += (v.x + v.y) + (v.z + v.w);
    }
#pragma unroll
    for (int o = 16; o > 0; o >>= 1)
        s += __shfl_xor_sync(0xffffffffu, s, o);

    __shared__ float ws[8];
    if ((tid & 31) == 0) ws[tid >> 5] = s;
    __syncthreads();
    if (tid < 8) {
        float t = ws[tid];
#pragma unroll
        for (int o = 4; o > 0; o >>= 1)
            t += __shfl_xor_sync(0x000000ffu, t, o);
        if (tid == 0) g_part[plane * 2 + half] = t;
    }
}

// ---------------------------------------------------------------------------
// Mid body: y1[b][r] = relu6((w_guide[r,:] @ sums[b]) / HW), one warp per r.
// ---------------------------------------------------------------------------
__device__ __forceinline__ void mid_body(const float* __restrict__ w_guide,
                                         int b, int r, int lane) {
    const float4* __restrict__ row =
        reinterpret_cast<const float4*>(w_guide + (size_t)r * CC);
    const float4* __restrict__ pp =
        reinterpret_cast<const float4*>(g_part + (size_t)b * CC * 2);

    float acc = 0.0f;
#pragma unroll
    for (int j = 0; j < 4; ++j) {
        float4 w  = row[lane + 32 * j];
        float4 a0 = pp[2 * (lane + 32 * j)];
        float4 a1 = pp[2 * (lane + 32 * j) + 1];
        acc = fmaf(w.x, a0.x + a0.y, acc);
        acc = fmaf(w.y, a0.z + a0.w, acc);
        acc = fmaf(w.z, a1.x + a1.y, acc);
        acc = fmaf(w.w, a1.z + a1.w, acc);
    }
#pragma unroll
    for (int o = 16; o > 0; o >>= 1)
        acc += __shfl_xor_sync(0xffffffffu, acc, o);
    if (lane == 0) {
        float v = acc * (1.0f / (float)HW);
        g_y1[b * RR + r] = fminf(fmaxf(v, 0.0f), 6.0f);
    }
}

// ---------------------------------------------------------------------------
// Role helpers. h = half-batch segment index (0..15): batch b = h>>1,
// channel base (h&1)*256; i in [0,512) -> plane (i>>1), half (i&1).
// ---------------------------------------------------------------------------
__device__ __forceinline__ void do_red(const float* __restrict__ x,
                                       int h, int i, int tid) {
    const int b = h >> 1;
    half_reduce(x, b * CC + (h & 1) * (CC / 2) + (i >> 1), i & 1, tid);
    if (tid == 0) {
        __threadfence();
        atomicAdd(&g_redCnt[b], 1);
    }
}

__device__ __forceinline__ void do_mid(const float* __restrict__ w_guide,
                                       int b, int m, int tid) {
    if (tid == 0)
        while (*(volatile int*)&g_redCnt[b] < REDTOT) __nanosleep(64);
    __syncthreads();
    mid_body(w_guide, b, m * 8 + (tid >> 5), tid & 31);
    __syncthreads();
    if (tid == 0) {
        __threadfence();
        const int t = atomicAdd(&g_midArr[b], 1);
        atomicAdd(&g_y1rdy[b], 1);
        if (t == MIDN - 1) {            // last mid: reset red machinery
            g_redCnt[b] = 0;
            g_midArr[b] = 0;
        }
    }
}

// ---------------------------------------------------------------------------
// ADD with LOAD-BEFORE-WAIT: the first 4 float4 per thread are issued into
// registers BEFORE the y1 dependency spin, so a waiting CTA has already
// injected half its DRAM/L2 read traffic. The spin then only delays stores.
// Evict-first reads (dead after) and stores (protect the resident batch).
// ---------------------------------------------------------------------------
__device__ __forceinline__ void do_add(
    const float* __restrict__ x, float* __restrict__ out,
    const float* __restrict__ w_fuse,
    const float* __restrict__ bn_gamma, const float* __restrict__ bn_beta,
    const float* __restrict__ bn_mean,  const float* __restrict__ bn_var,
    int h, int i, int tid) {
    const int b    = h >> 1;
    const int c    = (h & 1) * (CC / 2) + (i >> 1);
    const int half = i & 1;
    const int plane = b * CC + c;
    const float4* __restrict__ p =
        reinterpret_cast<const float4*>(x + (size_t)plane * HW) + half * HV;
    float4* __restrict__ o =
        reinterpret_cast<float4*>(out + (size_t)plane * HW) + half * HV;

    // ---- issue first half of reads (in flight across the wait) ----
    float4 v0 = __ldcs(&p[tid]);
    float4 v1 = __ldcs(&p[tid + 256]);
    float4 v2 = __ldcs(&p[tid + 512]);
    float4 v3 = __ldcs(&p[tid + 768]);

    // ---- dependency wait + ticket (tid 0 only) ----
    if (tid == 0) {
        while (*(volatile int*)&g_y1rdy[b] < MIDN) __nanosleep(64);
        const int u = atomicAdd(&g_addArr[b], 1);
        if (u == ADDTOT - 1) {          // last add: reset y1 machinery
            g_y1rdy[b]  = 0;
            g_addArr[b] = 0;
        }
    }
    __syncthreads();

    // ---- bias = relu6(BN(dot(w_fuse[c,:], y1[b]))) by warp 0 ----
    __shared__ float bsh;
    const int lane = tid & 31;
    if (tid < 32) {
        const float4* __restrict__ row =
            reinterpret_cast<const float4*>(w_fuse + (size_t)c * RR);
        const float4* __restrict__ y14 =
            reinterpret_cast<const float4*>(g_y1 + b * RR);
        float4 w = row[lane];
        float4 y = y14[lane];
        float acc = w.x * y.x;
        acc = fmaf(w.y, y.y, acc);
        acc = fmaf(w.z, y.z, acc);
        acc = fmaf(w.w, y.w, acc);
#pragma unroll
        for (int oo = 16; oo > 0; oo >>= 1)
            acc += __shfl_xor_sync(0xffffffffu, acc, oo);
        if (lane == 0) {
            const float inv_std = rsqrtf(bn_var[c] + 1e-5f);
            float v = fmaf((acc - bn_mean[c]) * inv_std, bn_gamma[c], bn_beta[c]);
            bsh = fminf(fmaxf(v, 0.0f), 6.0f);
        }
    }
    __syncthreads();
    const float bias = bsh;

    // ---- drain buffered first half, then stream second half ----
    v0.x += bias; v0.y += bias; v0.z += bias; v0.w += bias;
    v1.x += bias; v1.y += bias; v1.z += bias; v1.w += bias;
    v2.x += bias; v2.y += bias; v2.z += bias; v2.w += bias;
    v3.x += bias; v3.y += bias; v3.z += bias; v3.w += bias;
    __stcs(&o[tid],       v0);
    __stcs(&o[tid + 256], v1);
    __stcs(&o[tid + 512], v2);
    __stcs(&o[tid + 768], v3);
#pragma unroll
    for (int j = 4; j < 8; ++j) {
        float4 v = __ldcs(&p[tid + j * 256]);
        v.x += bias; v.y += bias; v.z += bias; v.w += bias;
        __stcs(&o[tid + j * 256], v);
    }
}

// ---------------------------------------------------------------------------
// Mega kernel, half-batch depth-2 pipeline with load-before-wait adds:
//   red(0) | red(1)+mid(0) | k=2..15: [add(k-2) (even) x red(k) (odd)]
//   (+mid(k>>1) on odd k) | add(14) | add(15)
// Producers precede consumers in bid order; root producers never wait.
// ---------------------------------------------------------------------------
__global__ __launch_bounds__(256) void mega_kernel(
    const float* __restrict__ x, float* __restrict__ out,
    const float* __restrict__ w_guide,
    const float* __restrict__ w_fuse,
    const float* __restrict__ bn_gamma, const float* __restrict__ bn_beta,
    const float* __restrict__ bn_mean,  const float* __restrict__ bn_var) {
    const int bid = blockIdx.x;
    const int tid = threadIdx.x;

    int k = 0;
    while (bid >= BSTART[k + 1]) ++k;       // <=18 constant-mem iterations
    const int off = bid - BSTART[k];

    if (k == 0) {
        do_red(x, 0, off, tid);
    } else if (k == 1) {
        if (off < SRED) do_red(x, 1, off, tid);
        else            do_mid(w_guide, 0, off - SRED, tid);
    } else if (k < SEGS) {
        if (off < 2 * SRED) {
            const int i = off >> 1;
            if (off & 1)
                do_red(x, k, i, tid);
            else
                do_add(x, out, w_fuse, bn_gamma, bn_beta, bn_mean, bn_var,
                       k - 2, i, tid);
        } else {
            do_mid(w_guide, k >> 1, off - 2 * SRED, tid);
        }
    } else {
        do_add(x, out, w_fuse, bn_gamma, bn_beta, bn_mean, bn_var,
               k - 2, off, tid);
    }
}

extern "C" void kernel_launch(void* const* d_in, const int* in_sizes, int n_in,
                              void* d_out, int out_size) {
    const float* x        = (const float*)d_in[0];
    const float* w_guide  = (const float*)d_in[1];
    const float* w_fuse   = (const float*)d_in[2];
    const float* bn_gamma = (const float*)d_in[3];
    const float* bn_beta  = (const float*)d_in[4];
    const float* bn_mean  = (const float*)d_in[5];
    const float* bn_var   = (const float*)d_in[6];
    float* out = (float*)d_out;

    mega_kernel<<<GRID, 256>>>(x, out, w_guide, w_fuse,
                               bn_gamma, bn_beta, bn_mean, bn_var);
}